// round 2
// baseline (speedup 1.0000x reference)
#include <cuda_runtime.h>
#include <math.h>

#define BB   16
#define CIN  20
#define HH   256
#define WW   256
#define WD   64
#define M1   16
#define M2   16
#define NL   4
#define FCH  128
#define COUTC 20
#define NPIX 65536

// ---------------- scratch (device globals; no allocation allowed) -------------
__device__ float g_h  [BB*WD*NPIX];          // activations, in-place per layer (268 MB)
__device__ float g_Gx [BB*WD*HH*32];         // after x-DFT: [row=(bc*256+y)][32]
__device__ float g_Xft[BB*WD*512*2];         // [(b*64+c)*512 + mode] complex
__device__ float g_T  [BB*WD*512*2];         // mixed modes
__device__ float g_G2 [BB*WD*HH*32];         // after inverse-y: [((b*64+o)*256+y)*32]
// basis tables
__device__ float g_bFx[WW*32];               // [x*32 + 2k(+1)]  e^{-i 2pi k x/256}
__device__ float g_bFy[HH*64];               // [y*64 + 2m(+1)]  e^{-i 2pi ky y/256}
__device__ float g_bIy[64*HH];               // TRANSPOSED [t*256+y], t=2m: cos, 2m+1: +sin
__device__ float g_bIx[32*WW];               // TRANSPOSED [t*256+x], t=2k: c*cos/65536, 2k+1: -c*sin/65536

__device__ __forceinline__ float gelu_f(float v) {
    return 0.5f * v * (1.0f + erff(v * 0.70710678118654752440f));
}

// ---------------- init basis --------------------------------------------------
__global__ void k_init_basis() {
    int t = blockIdx.x * blockDim.x + threadIdx.x;
    if (t < WW * M2) {
        int x = t >> 4, k = t & 15;
        double ang = (double)(k * x) / 128.0;   // theta / pi
        double s, c; sincospi(ang, &s, &c);
        g_bFx[x * 32 + 2 * k]     = (float)c;
        g_bFx[x * 32 + 2 * k + 1] = (float)(-s);
        double cc = (k == 0) ? 1.0 : 2.0;
        g_bIx[(2 * k) * WW + x]     = (float)( cc * c / 65536.0);
        g_bIx[(2 * k + 1) * WW + x] = (float)(-cc * s / 65536.0);
    }
    if (t < HH * 32) {
        int y = t >> 5, m = t & 31;
        int ky = (m < 16) ? m : (m + 224);      // m=16 -> ky=240 (= -16) ... m=31 -> 255
        double ang = (double)(ky * y) / 128.0;
        double s, c; sincospi(ang, &s, &c);
        g_bFy[y * 64 + 2 * m]     = (float)c;
        g_bFy[y * 64 + 2 * m + 1] = (float)(-s);
        g_bIy[(2 * m) * HH + y]     = (float)c;
        g_bIy[(2 * m + 1) * HH + y] = (float)s;
    }
}

// ---------------- lift: h = fc0(x) -------------------------------------------
__global__ void __launch_bounds__(256) k_lift(const float* __restrict__ x,
                                              const float* __restrict__ w,
                                              const float* __restrict__ b) {
    __shared__ float ws[WD * CIN];
    __shared__ float bs[WD];
    int tid = threadIdx.x;
    for (int i = tid; i < WD * CIN; i += 256) ws[i] = w[i];
    if (tid < WD) bs[tid] = b[tid];
    __syncthreads();
    int pix = blockIdx.x * 256 + tid;
    int bb = pix >> 16;
    int p  = pix & 65535;
    float in[CIN];
#pragma unroll
    for (int c = 0; c < CIN; c++) in[c] = x[(bb * CIN + c) * NPIX + p];
#pragma unroll 4
    for (int d = 0; d < WD; d++) {
        float acc = bs[d];
#pragma unroll
        for (int c = 0; c < CIN; c++) acc += in[c] * ws[d * CIN + c];
        g_h[(bb * WD + d) * NPIX + p] = acc;
    }
}

// ---------------- forward DFT along x: Gx[R,32] = h[R,256] * Bx[256,32] -------
__global__ void __launch_bounds__(256) k_fwdX() {
    __shared__ float As[256 * 33];
    __shared__ float Bs[32 * 33];
    int rowbase = blockIdx.x * 256;
    int tid = threadIdx.x;
    int ri = tid >> 3;   // 0..31  (rows ri + 32j)
    int ci = tid & 7;    // 0..7   (cols ci*4 .. ci*4+3)
    float acc[8][4];
#pragma unroll
    for (int j = 0; j < 8; j++)
#pragma unroll
        for (int c = 0; c < 4; c++) acc[j][c] = 0.f;
    for (int xc = 0; xc < 8; xc++) {
        if (xc) __syncthreads();
        for (int l = tid; l < 8192; l += 256) {
            int rr = l >> 5, xx = l & 31;
            As[rr * 33 + xx] = g_h[(rowbase + rr) * 256 + xc * 32 + xx];
        }
        for (int l = tid; l < 1024; l += 256) {
            int xx = l >> 5, t = l & 31;
            Bs[xx * 33 + t] = g_bFx[(xc * 32 + xx) * 32 + t];
        }
        __syncthreads();
#pragma unroll 4
        for (int xx = 0; xx < 32; xx++) {
            float b0 = Bs[xx * 33 + ci * 4 + 0];
            float b1 = Bs[xx * 33 + ci * 4 + 1];
            float b2 = Bs[xx * 33 + ci * 4 + 2];
            float b3 = Bs[xx * 33 + ci * 4 + 3];
#pragma unroll
            for (int j = 0; j < 8; j++) {
                float a = As[(ri + 32 * j) * 33 + xx];
                acc[j][0] += a * b0; acc[j][1] += a * b1;
                acc[j][2] += a * b2; acc[j][3] += a * b3;
            }
        }
    }
#pragma unroll
    for (int j = 0; j < 8; j++) {
        int row = rowbase + ri + 32 * j;
        *(float4*)(g_Gx + row * 32 + ci * 4) =
            make_float4(acc[j][0], acc[j][1], acc[j][2], acc[j][3]);
    }
}

// ---------------- forward DFT along y (256 -> 32 modes), complex --------------
__global__ void __launch_bounds__(512) k_fwdY() {
    __shared__ float s[HH * 32];   // 32 KB
    int bc = blockIdx.x;
    const float* src = g_Gx + bc * HH * 32;
    for (int l = threadIdx.x; l < HH * 32; l += 512) s[l] = src[l];
    __syncthreads();
    int t = threadIdx.x;          // mode = m*16 + k
    int m = t >> 4, k = t & 15;
    float re = 0.f, im = 0.f;
    for (int y = 0; y < HH; y++) {
        float2 g = *(const float2*)(s + y * 32 + 2 * k);
        float2 w = *(const float2*)(g_bFy + y * 64 + 2 * m);
        re += g.x * w.x - g.y * w.y;
        im += g.x * w.y + g.y * w.x;
    }
    *(float2*)(g_Xft + (bc * 512 + t) * 2) = make_float2(re, im);
}

// ---------------- channel mix per mode: T[b,o] = sum_i X[b,i] * W[i,o] --------
__global__ void __launch_bounds__(256) k_mix(const float* __restrict__ w1r,
                                             const float* __restrict__ w1i,
                                             const float* __restrict__ w2r,
                                             const float* __restrict__ w2i,
                                             int layer) {
    __shared__ float Ws[WD * WD * 2];   // 32 KB, [ (i*64+o)*2 ]
    __shared__ float Xs[BB * WD * 2];   // 8 KB,  [ (b*64+i)*2 ]
    int mode = blockIdx.x;              // 0..511
    int m = mode >> 4;
    const float* wr; const float* wi; int off;
    if (m < 16) { wr = w1r; wi = w1i; off = mode; }
    else        { wr = w2r; wi = w2i; off = mode - 256; }
    int lbase = layer * WD * WD * 256;
    for (int l = threadIdx.x; l < WD * WD; l += 256) {
        Ws[l * 2]     = wr[lbase + l * 256 + off];
        Ws[l * 2 + 1] = wi[lbase + l * 256 + off];
    }
    for (int l = threadIdx.x; l < BB * WD; l += 256) {
        float2 v = *(const float2*)(g_Xft + (l * 512 + mode) * 2);
        Xs[l * 2]     = v.x;
        Xs[l * 2 + 1] = v.y;
    }
    __syncthreads();
    int o  = threadIdx.x & 63;
    int bq = threadIdx.x >> 6;    // 0..3 -> b = bq*4 + q
    float ar[4] = {0, 0, 0, 0}, ai[4] = {0, 0, 0, 0};
    for (int i = 0; i < WD; i++) {
        float2 w = *(const float2*)(Ws + (i * 64 + o) * 2);
#pragma unroll
        for (int q = 0; q < 4; q++) {
            int b = bq * 4 + q;
            float2 xv = *(const float2*)(Xs + (b * 64 + i) * 2);
            ar[q] += xv.x * w.x - xv.y * w.y;
            ai[q] += xv.x * w.y + xv.y * w.x;
        }
    }
#pragma unroll
    for (int q = 0; q < 4; q++) {
        int b = bq * 4 + q;
        *(float2*)(g_T + ((b * 64 + o) * 512 + mode) * 2) = make_float2(ar[q], ai[q]);
    }
}

// ---------------- inverse DFT along y (32 modes -> 256), complex --------------
__global__ void __launch_bounds__(256) k_invY() {
    __shared__ float Ts[1024];
    __shared__ float smt[256 * 33];
    int bo = blockIdx.x;
    for (int l = threadIdx.x; l < 1024; l += 256) Ts[l] = g_T[bo * 1024 + l];
    __syncthreads();
    int y = threadIdx.x;
    float acc[32];
#pragma unroll
    for (int i = 0; i < 32; i++) acc[i] = 0.f;
#pragma unroll 2
    for (int m = 0; m < 32; m++) {
        float cr = g_bIy[(2 * m) * HH + y];
        float ci = g_bIy[(2 * m + 1) * HH + y];
#pragma unroll
        for (int k = 0; k < 16; k++) {
            float tr = Ts[(m * 16 + k) * 2], ti = Ts[(m * 16 + k) * 2 + 1];
            acc[2 * k]     += tr * cr - ti * ci;
            acc[2 * k + 1] += tr * ci + ti * cr;
        }
    }
#pragma unroll
    for (int u = 0; u < 32; u++) smt[y * 33 + u] = acc[u];
    __syncthreads();
    float* dst = g_G2 + bo * 8192;
    for (int l = threadIdx.x; l < 8192; l += 256)
        dst[l] = smt[(l >> 5) * 33 + (l & 31)];
}

// ---------------- fused: inverse-x + 1x1 conv + bias (+GELU), in place -------
#define FUSE_SMEM ((16384 + 4096 + 2048 + 64) * 4)
__global__ void __launch_bounds__(256) k_fuse(const float* __restrict__ pw_w,
                                              const float* __restrict__ pw_b,
                                              int layer, int apply_gelu) {
    extern __shared__ float sm[];
    float* in_s = sm;               // 64*256
    float* w_s  = sm + 16384;       // 64*64  [i*64+o]
    float* g2_s = w_s + 4096;       // 64*32  [o*32+t]
    float* b_s  = g2_s + 2048;      // 64
    int bb = blockIdx.x >> 8;
    int y  = blockIdx.x & 255;
    int tid = threadIdx.x;
    const float* hrow = g_h + (bb * WD) * NPIX + y * 256;
    for (int l = tid; l < 16384; l += 256) {
        int i = l >> 8, x = l & 255;
        in_s[l] = hrow[i * NPIX + x];
    }
    for (int l = tid; l < 4096; l += 256) {
        int i = l >> 6, o = l & 63;
        w_s[l] = pw_w[(layer * WD + o) * WD + i];
    }
    if (tid < WD) b_s[tid] = pw_b[layer * WD + tid];
    {
        const float* g2row = g_G2 + (bb * WD) * 8192 + y * 32;
        for (int l = tid; l < 2048; l += 256) {
            int o = l >> 5, t = l & 31;
            g2_s[l] = g2row[o * 8192 + t];
        }
    }
    __syncthreads();
    int lane = tid & 31;
    int to   = tid >> 5;           // o-group 0..7, constant within warp
    int x0   = lane * 8;
    float acc[8][8];
#pragma unroll
    for (int v = 0; v < 8; v++) {
        float bv = b_s[to * 8 + v];
#pragma unroll
        for (int u = 0; u < 8; u++) acc[v][u] = bv;
    }
    // pointwise conv
    for (int i = 0; i < 64; i++) {
        float4 h0 = *(const float4*)(in_s + i * 256 + x0);
        float4 h1 = *(const float4*)(in_s + i * 256 + x0 + 4);
        float4 w0 = *(const float4*)(w_s + i * 64 + to * 8);
        float4 w1 = *(const float4*)(w_s + i * 64 + to * 8 + 4);
        float hv[8] = {h0.x, h0.y, h0.z, h0.w, h1.x, h1.y, h1.z, h1.w};
        float wv[8] = {w0.x, w0.y, w0.z, w0.w, w1.x, w1.y, w1.z, w1.w};
#pragma unroll
        for (int v = 0; v < 8; v++)
#pragma unroll
            for (int u = 0; u < 8; u++) acc[v][u] += hv[u] * wv[v];
    }
    // spectral inverse-x
    for (int t = 0; t < 32; t++) {
        float4 c0 = __ldg((const float4*)(g_bIx + t * 256 + x0));
        float4 c1 = __ldg((const float4*)(g_bIx + t * 256 + x0 + 4));
        float cv[8] = {c0.x, c0.y, c0.z, c0.w, c1.x, c1.y, c1.z, c1.w};
        float gv[8];
#pragma unroll
        for (int v = 0; v < 8; v++) gv[v] = g2_s[(to * 8 + v) * 32 + t];
#pragma unroll
        for (int v = 0; v < 8; v++)
#pragma unroll
            for (int u = 0; u < 8; u++) acc[v][u] += gv[v] * cv[u];
    }
    float* orow = g_h + (bb * WD) * NPIX + y * 256;
#pragma unroll
    for (int v = 0; v < 8; v++) {
        if (apply_gelu) {
#pragma unroll
            for (int u = 0; u < 8; u++) acc[v][u] = gelu_f(acc[v][u]);
        }
        int o = to * 8 + v;
        *(float4*)(orow + o * NPIX + x0) =
            make_float4(acc[v][0], acc[v][1], acc[v][2], acc[v][3]);
        *(float4*)(orow + o * NPIX + x0 + 4) =
            make_float4(acc[v][4], acc[v][5], acc[v][6], acc[v][7]);
    }
}

// ---------------- head: fc1(64->128)+GELU, fc2(128->20), fused ----------------
#define HEAD_SMEM ((16384 + 8192 + 8192 + 2560 + 128 + 32) * 4)
__global__ void __launch_bounds__(256) k_head(const float* __restrict__ w1,
                                              const float* __restrict__ b1,
                                              const float* __restrict__ w2,
                                              const float* __restrict__ b2,
                                              float* __restrict__ out) {
    extern __shared__ float sm[];
    float* h_s   = sm;                 // 64*256
    float* w1_s  = sm + 16384;         // 128*64  [d*64+i]
    float* hid_s = w1_s + 8192;        // 32*256 chunk
    float* w2_s  = hid_s + 8192;       // 20*128  [e*128+d]
    float* b1_s  = w2_s + 2560;        // 128
    float* b2_s  = b1_s + 128;         // 20
    int bb = blockIdx.x >> 8;
    int y  = blockIdx.x & 255;
    int tid = threadIdx.x;
    for (int l = tid; l < 16384; l += 256) {
        int i = l >> 8, x = l & 255;
        h_s[l] = g_h[(bb * WD + i) * NPIX + y * 256 + x];
    }
    for (int l = tid; l < 8192; l += 256) w1_s[l] = w1[l];
    for (int l = tid; l < 2560; l += 256) w2_s[l] = w2[l];
    if (tid < 128) b1_s[tid] = b1[tid];
    if (tid < 20)  b2_s[tid] = b2[tid];
    __syncthreads();
    float acc2[COUTC];
#pragma unroll
    for (int e = 0; e < COUTC; e++) acc2[e] = 0.f;
    int tx = tid & 31, td = tid >> 5, x0 = tx * 8;
    for (int chunk = 0; chunk < 4; chunk++) {
        float a[4][8];
#pragma unroll
        for (int v = 0; v < 4; v++) {
            float bv = b1_s[chunk * 32 + td * 4 + v];
#pragma unroll
            for (int u = 0; u < 8; u++) a[v][u] = bv;
        }
        for (int i = 0; i < 64; i++) {
            float4 h0 = *(const float4*)(h_s + i * 256 + x0);
            float4 h1 = *(const float4*)(h_s + i * 256 + x0 + 4);
            float hv[8] = {h0.x, h0.y, h0.z, h0.w, h1.x, h1.y, h1.z, h1.w};
#pragma unroll
            for (int v = 0; v < 4; v++) {
                float wv = w1_s[(chunk * 32 + td * 4 + v) * 64 + i];
#pragma unroll
                for (int u = 0; u < 8; u++) a[v][u] += hv[u] * wv;
            }
        }
#pragma unroll
        for (int v = 0; v < 4; v++) {
#pragma unroll
            for (int u = 0; u < 8; u++) a[v][u] = gelu_f(a[v][u]);
            *(float4*)(hid_s + (td * 4 + v) * 256 + x0) =
                make_float4(a[v][0], a[v][1], a[v][2], a[v][3]);
            *(float4*)(hid_s + (td * 4 + v) * 256 + x0 + 4) =
                make_float4(a[v][4], a[v][5], a[v][6], a[v][7]);
        }
        __syncthreads();
        for (int c = 0; c < 32; c++) {
            float hv = hid_s[c * 256 + tid];
#pragma unroll
            for (int e = 0; e < COUTC; e++)
                acc2[e] += hv * w2_s[e * 128 + chunk * 32 + c];
        }
        __syncthreads();
    }
    float* orow = out + (bb * COUTC) * NPIX + y * 256 + tid;
#pragma unroll
    for (int e = 0; e < COUTC; e++) orow[e * NPIX] = acc2[e] + b2_s[e];
}

// ---------------- launch ------------------------------------------------------
extern "C" void kernel_launch(void* const* d_in, const int* in_sizes, int n_in,
                              void* d_out, int out_size) {
    const float* x    = (const float*)d_in[0];
    const float* w1r  = (const float*)d_in[1];
    const float* w1i  = (const float*)d_in[2];
    const float* w2r  = (const float*)d_in[3];
    const float* w2i  = (const float*)d_in[4];
    const float* pw_w = (const float*)d_in[5];
    const float* pw_b = (const float*)d_in[6];
    const float* fc0w = (const float*)d_in[7];
    const float* fc0b = (const float*)d_in[8];
    const float* fc1w = (const float*)d_in[9];
    const float* fc1b = (const float*)d_in[10];
    const float* fc2w = (const float*)d_in[11];
    const float* fc2b = (const float*)d_in[12];
    float* out = (float*)d_out;

    cudaFuncSetAttribute(k_fuse, cudaFuncAttributeMaxDynamicSharedMemorySize, FUSE_SMEM);
    cudaFuncSetAttribute(k_head, cudaFuncAttributeMaxDynamicSharedMemorySize, HEAD_SMEM);

    k_init_basis<<<32, 256>>>();
    k_lift<<<4096, 256>>>(x, fc0w, fc0b);
    for (int l = 0; l < NL; l++) {
        k_fwdX<<<1024, 256>>>();
        k_fwdY<<<1024, 512>>>();
        k_mix<<<512, 256>>>(w1r, w1i, w2r, w2i, l);
        k_invY<<<1024, 256>>>();
        k_fuse<<<4096, 256, FUSE_SMEM>>>(pw_w, pw_b, l, (l < NL - 1) ? 1 : 0);
    }
    k_head<<<4096, 256, HEAD_SMEM>>>(fc1w, fc1b, fc2w, fc2b, out);
}